// round 2
// baseline (speedup 1.0000x reference)
#include <cuda_runtime.h>
#include <math.h>

// KAN linear fused kernel:
//   out[b,o] = sum_i silu(x[b,i]) * scale_base[o,i]
//            + sum_{i,g} Bspline_g(x[b,i]) * coeff[o,i,g] * scale_spline
// Treated as C[M,N] = A[M,K] @ W[K,N] with M=8192, N=1024, K=1024*12,
// where A is generated on the fly (silu + 11 cubic B-spline bases per input).

#define TOKENS  8192
#define IN_DIM  1024
#define OUT_DIM 1024
#define GK      11      // grid_size + spline order
#define NB0     14      // number of order-0 bases (15 knots)
#define NKNOT   15

#define BM 128
#define BN 128
#define IC 8            // input channels per K-chunk
#define BK (IC * 12)    // 96 K-slots per chunk
#define NTHREADS 256

#define SMEM_FLOATS (BK * BM + BK * BN)
#define SMEM_BYTES  (SMEM_FLOATS * 4)

__global__ void __launch_bounds__(NTHREADS, 2)
kan_fused_kernel(const float* __restrict__ x,
                 const float* __restrict__ grid,
                 const float* __restrict__ coeff,
                 const float* __restrict__ scale_base,
                 const float* __restrict__ scale_spline,
                 float* __restrict__ out)
{
    extern __shared__ float smem[];
    float (*As)[BM] = (float (*)[BM])smem;                 // [BK][BM]
    float (*Ws)[BN] = (float (*)[BN])(smem + BK * BM);     // [BK][BN]

    const float ss = scale_spline[0];

    const int m0 = blockIdx.y * BM;
    const int n0 = blockIdx.x * BN;
    const int tid = threadIdx.x;
    const int tx = tid & 15;   // output-col group: cols tx*8 .. tx*8+7
    const int ty = tid >> 4;   // token-row group:  rows ty*8 .. ty*8+7

    float acc[8][8];
    #pragma unroll
    for (int a = 0; a < 8; a++)
        #pragma unroll
        for (int b = 0; b < 8; b++) acc[a][b] = 0.0f;

    for (int i0 = 0; i0 < IN_DIM; i0 += IC) {
        // ------------------------------------------------------------------
        // Phase 1: generate A features into smem.
        // 1024 (token, input) pairs; each thread handles 4 with one float4 x load.
        // ------------------------------------------------------------------
        {
            const int p  = tid * 4;
            const int bl = p >> 3;        // local token 0..127
            const int il = p & 7;         // 0 or 4
            const float4 xv = *(const float4*)(x + (size_t)(m0 + bl) * IN_DIM + i0 + il);
            float xs[4] = {xv.x, xv.y, xv.z, xv.w};

            #pragma unroll
            for (int r = 0; r < 4; r++) {
                const int ii = i0 + il + r;
                const float xx = xs[r];

                // silu(x) = x * sigmoid(x)
                const float sil = xx / (1.0f + __expf(-xx));

                // knots for this input channel
                float g[NKNOT];
                #pragma unroll
                for (int j = 0; j < NKNOT; j++)
                    g[j] = __ldg(grid + (size_t)ii * NKNOT + j);

                // order-0 indicator bases
                float bas[NB0];
                #pragma unroll
                for (int j = 0; j < NB0; j++)
                    bas[j] = (xx >= g[j] && xx < g[j + 1]) ? 1.0f : 0.0f;

                // Cox-de Boor recursion to order 3
                #pragma unroll
                for (int kk = 1; kk <= 3; kk++) {
                    #pragma unroll
                    for (int j = 0; j < NB0 - 1; j++) {
                        if (j < NB0 - kk) {
                            float left  = (xx - g[j])        / (g[j + kk]     - g[j]);
                            float right = (g[j + kk + 1] - xx) / (g[j + kk + 1] - g[j + 1]);
                            bas[j] = left * bas[j] + right * bas[j + 1];
                        }
                    }
                }

                const int kbase = (il + r) * 12;
                As[kbase][bl] = sil;
                #pragma unroll
                for (int j = 0; j < GK; j++)
                    As[kbase + 1 + j][bl] = bas[j];
            }
        }

        // ------------------------------------------------------------------
        // Phase 2: load W tile into smem (scale_base into slot 0, coeff*ss 1..11).
        // 1024 (output, input) pairs; each thread handles 4.
        // ------------------------------------------------------------------
        {
            const int p  = tid * 4;
            const int ol = p >> 3;        // local output 0..127
            const int il = p & 7;         // 0 or 4
            const int o  = n0 + ol;

            #pragma unroll
            for (int r = 0; r < 4; r++) {
                const int ii = i0 + il + r;
                const int kbase = (il + r) * 12;
                Ws[kbase][ol] = __ldg(scale_base + (size_t)o * IN_DIM + ii);
                const float* cr = coeff + ((size_t)o * IN_DIM + ii) * GK;
                #pragma unroll
                for (int j = 0; j < GK; j++)
                    Ws[kbase + 1 + j][ol] = __ldg(cr + j) * ss;
            }
        }

        __syncthreads();

        // ------------------------------------------------------------------
        // Phase 3: 8x8 register-tile FMA over BK=96 K-slots
        // ------------------------------------------------------------------
        #pragma unroll 4
        for (int k = 0; k < BK; k++) {
            float a[8], w[8];
            *(float4*)&a[0] = *(const float4*)&As[k][ty * 8];
            *(float4*)&a[4] = *(const float4*)&As[k][ty * 8 + 4];
            *(float4*)&w[0] = *(const float4*)&Ws[k][tx * 8];
            *(float4*)&w[4] = *(const float4*)&Ws[k][tx * 8 + 4];
            #pragma unroll
            for (int mi = 0; mi < 8; mi++)
                #pragma unroll
                for (int ni = 0; ni < 8; ni++)
                    acc[mi][ni] = fmaf(a[mi], w[ni], acc[mi][ni]);
        }

        __syncthreads();
    }

    // ----------------------------------------------------------------------
    // Epilogue: write 8x8 tile
    // ----------------------------------------------------------------------
    #pragma unroll
    for (int mi = 0; mi < 8; mi++) {
        const int m = m0 + ty * 8 + mi;
        float* op = out + (size_t)m * OUT_DIM + n0 + tx * 8;
        float4 v0 = make_float4(acc[mi][0], acc[mi][1], acc[mi][2], acc[mi][3]);
        float4 v1 = make_float4(acc[mi][4], acc[mi][5], acc[mi][6], acc[mi][7]);
        *(float4*)op       = v0;
        *(float4*)(op + 4) = v1;
    }
}

extern "C" void kernel_launch(void* const* d_in, const int* in_sizes, int n_in,
                              void* d_out, int out_size)
{
    const float* x           = (const float*)d_in[0];
    const float* grid        = (const float*)d_in[1];
    const float* coeff       = (const float*)d_in[2];
    const float* scale_base  = (const float*)d_in[3];
    const float* scale_spl   = (const float*)d_in[4];
    float* out               = (float*)d_out;

    static bool attr_set = false;
    if (!attr_set) {
        cudaFuncSetAttribute(kan_fused_kernel,
                             cudaFuncAttributeMaxDynamicSharedMemorySize,
                             SMEM_BYTES);
        attr_set = true;
    }

    dim3 grid_dim(OUT_DIM / BN, TOKENS / BM);   // (8, 64)
    kan_fused_kernel<<<grid_dim, NTHREADS, SMEM_BYTES>>>(
        x, grid, coeff, scale_base, scale_spl, out);
}

// round 4
// speedup vs baseline: 3.9905x; 3.9905x over previous
#include <cuda_runtime.h>
#include <cuda_bf16.h>
#include <stdint.h>

#define TOKENS  8192
#define IN_DIM  1024
#define OUT_DIM 1024
#define NKNOT   15
#define KDIM    12288            // IN_DIM * 12 features (silu + 11 bases)

__device__ __nv_bfloat16 g_Ahi[(size_t)TOKENS * KDIM];
__device__ __nv_bfloat16 g_Alo[(size_t)TOKENS * KDIM];
__device__ __nv_bfloat16 g_Whi[(size_t)OUT_DIM * KDIM];
__device__ __nv_bfloat16 g_Wlo[(size_t)OUT_DIM * KDIM];

// ---------------- helpers ----------------
__device__ __forceinline__ uint32_t smem_u32(const void* p) {
    uint32_t a;
    asm("{ .reg .u64 t; cvta.to.shared.u64 t, %1; cvt.u32.u64 %0, t; }" : "=r"(a) : "l"(p));
    return a;
}
__device__ __forceinline__ void cpasync16(uint32_t dst, const void* src) {
    asm volatile("cp.async.cg.shared.global [%0], [%1], 16;" :: "r"(dst), "l"(src) : "memory");
}
#define CP_COMMIT() asm volatile("cp.async.commit_group;" ::: "memory")
#define CP_WAIT1()  asm volatile("cp.async.wait_group 1;" ::: "memory")
#define CP_WAIT0()  asm volatile("cp.async.wait_group 0;" ::: "memory")

__device__ __forceinline__ void ldsm4(uint32_t& r0, uint32_t& r1, uint32_t& r2, uint32_t& r3,
                                      uint32_t addr) {
    asm volatile("ldmatrix.sync.aligned.m8n8.x4.shared.b16 {%0,%1,%2,%3}, [%4];"
                 : "=r"(r0), "=r"(r1), "=r"(r2), "=r"(r3) : "r"(addr));
}
__device__ __forceinline__ void mma16816(float* c, const uint32_t* a, const uint32_t* b) {
    asm volatile("mma.sync.aligned.m16n8k16.row.col.f32.bf16.bf16.f32 "
                 "{%0,%1,%2,%3}, {%4,%5,%6,%7}, {%8,%9}, {%0,%1,%2,%3};"
                 : "+f"(c[0]), "+f"(c[1]), "+f"(c[2]), "+f"(c[3])
                 : "r"(a[0]), "r"(a[1]), "r"(a[2]), "r"(a[3]), "r"(b[0]), "r"(b[1]));
}

__device__ __forceinline__ void split2(float a, float b, uint32_t& hi, uint32_t& lo) {
    __nv_bfloat16 ah = __float2bfloat16(a), bh = __float2bfloat16(b);
    __nv_bfloat16 al = __float2bfloat16(a - __bfloat162float(ah));
    __nv_bfloat16 bl = __float2bfloat16(b - __bfloat162float(bh));
    hi = (uint32_t)__bfloat16_as_ushort(ah) | ((uint32_t)__bfloat16_as_ushort(bh) << 16);
    lo = (uint32_t)__bfloat16_as_ushort(al) | ((uint32_t)__bfloat16_as_ushort(bl) << 16);
}

// ---------------- Kernel 1: W prep ----------------
__global__ void __launch_bounds__(256) kan_wprep(const float* __restrict__ coeff,
                                                 const float* __restrict__ sb,
                                                 const float* __restrict__ ssp)
{
    const float ss = ssp[0];
    const int i = blockIdx.x * 256 + threadIdx.x;
    const int o = blockIdx.y;
    float v[12];
    v[0] = sb[(size_t)o * IN_DIM + i];
    const float* cr = coeff + ((size_t)o * IN_DIM + i) * 11;
    #pragma unroll
    for (int j = 0; j < 11; j++) v[1 + j] = cr[j] * ss;

    uint32_t hi[6], lo[6];
    #pragma unroll
    for (int p = 0; p < 6; p++) split2(v[2*p], v[2*p+1], hi[p], lo[p]);
    const size_t off = (size_t)o * KDIM + (size_t)i * 12;
    #pragma unroll
    for (int p = 0; p < 3; p++) {
        ((uint2*)(g_Whi + off))[p] = make_uint2(hi[2*p], hi[2*p+1]);
        ((uint2*)(g_Wlo + off))[p] = make_uint2(lo[2*p], lo[2*p+1]);
    }
}

// ---------------- Kernel 2: featurizer ----------------
__global__ void __launch_bounds__(256) kan_featurize(const float* __restrict__ x,
                                                     const float* __restrict__ grid)
{
    __shared__ float tab[32][55];  // 0..14 knots, 15..28 L1, 29..41 L2, 42..53 L3
    const int lane = threadIdx.x & 31;
    const int w    = threadIdx.x >> 5;
    const int i0   = blockIdx.x * 32;
    const int gi   = (i0 + lane) * NKNOT;

    for (int idx = w; idx < 54; idx += 8) {
        float val;
        if (idx < 15)      val = grid[gi + idx];
        else if (idx < 29) { int j = idx - 15; val = 1.0f / (grid[gi+j+1] - grid[gi+j]); }
        else if (idx < 42) { int j = idx - 29; val = 1.0f / (grid[gi+j+2] - grid[gi+j]); }
        else               { int j = idx - 42; val = 1.0f / (grid[gi+j+3] - grid[gi+j]); }
        tab[lane][idx] = val;
    }
    __syncthreads();

    const int t = blockIdx.y * 8 + w;
    const int i = i0 + lane;
    const float xx = x[(size_t)t * IN_DIM + i];

    float G[15];
    #pragma unroll
    for (int j = 0; j < 15; j++) G[j] = tab[lane][j];

    float bas[14];
    #pragma unroll
    for (int j = 0; j < 14; j++) bas[j] = (xx >= G[j] && xx < G[j+1]) ? 1.0f : 0.0f;
    #pragma unroll
    for (int j = 0; j < 13; j++)
        bas[j] = (xx - G[j]) * tab[lane][15+j] * bas[j] + (G[j+2] - xx) * tab[lane][16+j] * bas[j+1];
    #pragma unroll
    for (int j = 0; j < 12; j++)
        bas[j] = (xx - G[j]) * tab[lane][29+j] * bas[j] + (G[j+3] - xx) * tab[lane][30+j] * bas[j+1];
    #pragma unroll
    for (int j = 0; j < 11; j++)
        bas[j] = (xx - G[j]) * tab[lane][42+j] * bas[j] + (G[j+4] - xx) * tab[lane][43+j] * bas[j+1];

    float v[12];
    v[0] = xx / (1.0f + __expf(-xx));
    #pragma unroll
    for (int j = 0; j < 11; j++) v[1+j] = bas[j];

    uint32_t hi[6], lo[6];
    #pragma unroll
    for (int p = 0; p < 6; p++) split2(v[2*p], v[2*p+1], hi[p], lo[p]);
    const size_t off = (size_t)t * KDIM + (size_t)i * 12;
    #pragma unroll
    for (int p = 0; p < 3; p++) {
        ((uint2*)(g_Ahi + off))[p] = make_uint2(hi[2*p], hi[2*p+1]);
        ((uint2*)(g_Alo + off))[p] = make_uint2(lo[2*p], lo[2*p+1]);
    }
}

// ---------------- Kernel 3: GEMM (warp mma.sync, bf16 3-term split) ----------------
#define GM 128
#define GN 128
#define GBK 32
#define NIT (KDIM / GBK)          // 384
#define RSTRIDE 80                // bytes per smem row (32 halfs padded to 40)
#define ARR (128 * RSTRIDE)       // 10240 bytes per array
#define OFF_AH 0
#define OFF_AL (1 * ARR)
#define OFF_WH (2 * ARR)
#define OFF_WL (3 * ARR)
#define STG (4 * ARR)             // 40960 per stage
#define GEMM_SMEM (2 * STG)       // 81920

__device__ __forceinline__ void load_stage(uint32_t sbase, int s, int m0, int n0, int k0, int tid)
{
    const uint32_t tb = sbase + s * STG;
    // each array: 128 rows x 4 chunks(16B) = 512 chunks; 2 per thread per array
    #pragma unroll
    for (int r = 0; r < 2; r++) {
        const int c = tid + 256 * r;
        const int row = c >> 2, cc = c & 3;
        const uint32_t so = row * RSTRIDE + cc * 16;
        const size_t ga = (size_t)(m0 + row) * KDIM + k0 + cc * 8;
        const size_t gw = (size_t)(n0 + row) * KDIM + k0 + cc * 8;
        cpasync16(tb + OFF_AH + so, g_Ahi + ga);
        cpasync16(tb + OFF_AL + so, g_Alo + ga);
        cpasync16(tb + OFF_WH + so, g_Whi + gw);
        cpasync16(tb + OFF_WL + so, g_Wlo + gw);
    }
}

__global__ void __launch_bounds__(256) kan_gemm(float* __restrict__ out)
{
    extern __shared__ char smem[];
    const uint32_t sb = smem_u32(smem);
    const int tid  = threadIdx.x;
    const int lane = tid & 31;
    const int warp = tid >> 5;
    const int wm = warp >> 2;          // 0..1  -> m offset wm*64
    const int wn = warp & 3;           // 0..3  -> n offset wn*32
    const int m0 = blockIdx.y * GM;
    const int n0 = blockIdx.x * GN;

    float acc[4][4][4];
    #pragma unroll
    for (int mi = 0; mi < 4; mi++)
        #pragma unroll
        for (int ni = 0; ni < 4; ni++)
            #pragma unroll
            for (int q = 0; q < 4; q++) acc[mi][ni][q] = 0.0f;

    // ldmatrix address components (byte offsets within an array)
    const uint32_t a_row  = wm * 64 + (lane & 15);
    const uint32_t a_chunk = (lane >> 4) * 16;
    const uint32_t b_row  = wn * 32 + (lane & 7) + ((lane >> 4) << 3);
    const uint32_t b_chunk = ((lane >> 3) & 1) * 16;

    load_stage(sb, 0, m0, n0, 0, tid);
    CP_COMMIT();

    for (int it = 0; it < NIT; ++it) {
        const int s = it & 1;
        if (it + 1 < NIT) {
            load_stage(sb, s ^ 1, m0, n0, (it + 1) * GBK, tid);
            CP_COMMIT();
            CP_WAIT1();
        } else {
            CP_WAIT0();
        }
        __syncthreads();

        const uint32_t tb = sb + s * STG;
        #pragma unroll
        for (int ks = 0; ks < 2; ++ks) {
            const uint32_t kb = ks * 32;
            uint32_t bh[8], bl[8], a[16];
            // W hi/lo fragments: 2 ldmatrix.x4 each (n-tiles 2g, 2g+1)
            #pragma unroll
            for (int g = 0; g < 2; g++) {
                const uint32_t adr = (b_row + g * 16) * RSTRIDE + kb + b_chunk;
                ldsm4(bh[4*g], bh[4*g+1], bh[4*g+2], bh[4*g+3], tb + OFF_WH + adr);
                ldsm4(bl[4*g], bl[4*g+1], bl[4*g+2], bl[4*g+3], tb + OFF_WL + adr);
            }
            // A hi fragments: 4 ldmatrix.x4
            #pragma unroll
            for (int mi = 0; mi < 4; mi++) {
                const uint32_t adr = (a_row + mi * 16) * RSTRIDE + kb + a_chunk;
                ldsm4(a[4*mi], a[4*mi+1], a[4*mi+2], a[4*mi+3], tb + OFF_AH + adr);
            }
            #pragma unroll
            for (int mi = 0; mi < 4; mi++)
                #pragma unroll
                for (int ni = 0; ni < 4; ni++) {
                    mma16816(acc[mi][ni], &a[4*mi], &bh[2*ni]);   // Ah*Wh
                    mma16816(acc[mi][ni], &a[4*mi], &bl[2*ni]);   // Ah*Wl
                }
            // A lo fragments (overwrite a)
            #pragma unroll
            for (int mi = 0; mi < 4; mi++) {
                const uint32_t adr = (a_row + mi * 16) * RSTRIDE + kb + a_chunk;
                ldsm4(a[4*mi], a[4*mi+1], a[4*mi+2], a[4*mi+3], tb + OFF_AL + adr);
            }
            #pragma unroll
            for (int mi = 0; mi < 4; mi++)
                #pragma unroll
                for (int ni = 0; ni < 4; ni++)
                    mma16816(acc[mi][ni], &a[4*mi], &bh[2*ni]);   // Al*Wh
        }
        __syncthreads();
    }

    // epilogue
    const int cr = lane >> 2;           // 0..7
    const int cc = (lane & 3) * 2;      // 0,2,4,6
    #pragma unroll
    for (int mi = 0; mi < 4; mi++) {
        const int mrow = m0 + wm * 64 + mi * 16 + cr;
        #pragma unroll
        for (int ni = 0; ni < 4; ni++) {
            const int col = n0 + wn * 32 + ni * 8 + cc;
            *(float2*)(out + (size_t)mrow       * OUT_DIM + col) = make_float2(acc[mi][ni][0], acc[mi][ni][1]);
            *(float2*)(out + (size_t)(mrow + 8) * OUT_DIM + col) = make_float2(acc[mi][ni][2], acc[mi][ni][3]);
        }
    }
}

// ---------------- Launch ----------------
extern "C" void kernel_launch(void* const* d_in, const int* in_sizes, int n_in,
                              void* d_out, int out_size)
{
    const float* x     = (const float*)d_in[0];
    const float* grid  = (const float*)d_in[1];
    const float* coeff = (const float*)d_in[2];
    const float* sb    = (const float*)d_in[3];
    const float* ss    = (const float*)d_in[4];
    float* out         = (float*)d_out;

    cudaFuncSetAttribute(kan_gemm, cudaFuncAttributeMaxDynamicSharedMemorySize, GEMM_SMEM);

    kan_wprep<<<dim3(IN_DIM / 256, OUT_DIM), 256>>>(coeff, sb, ss);
    kan_featurize<<<dim3(IN_DIM / 32, TOKENS / 8), 256>>>(x, grid);
    kan_gemm<<<dim3(OUT_DIM / GN, TOKENS / GM), 256, GEMM_SMEM>>>(out);
}